// round 15
// baseline (speedup 1.0000x reference)
#include <cuda_runtime.h>
#include <cstdint>

// ---------------------------------------------------------------------------
// QuantumRNNCell fused persistent kernel, v15 (intra-warp pipelined stream)
//   out[b,h] = hx[b,h] + sum_j q[b,j] * fc_w[h,j] + fc_b[h]
// Block = 384 threads, 2 CTAs/SM:
//   warps 0..3  : sim warps (packed 2-rows/warp, analytic encoding), write q
//                 duplicated into a 2-slot smem ring (full=8 / empty=256
//                 mbarriers). Unchanged from R13/R14 (validated).
//   warps 4..11 : stream warps, direct LDG->FMA->STG, software-pipelined at
//                 half-tile (4-row) granularity: while FMAing one half, the
//                 other half's 4 LDG.128 are always in flight -> per-warp
//                 load stream never idles.
// ---------------------------------------------------------------------------

#define NQ 6
#define NLAYERS 3
#define HDIM 1024
#define TR 8
#define HT 4                     // half-tile rows
#define NSIMW 4
#define NTHREADS 384
#define SQROW 16                 // floats per sq row (12 used, padded)

// ---- mbarrier helpers -------------------------------------------------------
#define MBAR_INIT(addr, cnt) \
    asm volatile("mbarrier.init.shared.b64 [%0], %1;" :: "r"(addr), "r"(cnt) : "memory")
#define MBAR_ARRIVE(addr) \
    asm volatile("mbarrier.arrive.shared.b64 _, [%0];" :: "r"(addr) : "memory")
#define MBAR_WAIT(addr, parity) do {                                          \
    asm volatile(                                                             \
        "{\n\t.reg .pred P;\n\t"                                              \
        "WAIT_%=:\n\t"                                                        \
        "mbarrier.try_wait.parity.acquire.cta.shared::cta.b64 P, [%0], %1, 0x989680;\n\t" \
        "@P bra.uni DONE_%=;\n\t"                                             \
        "bra.uni WAIT_%=;\n\t"                                                \
        "DONE_%=:\n\t}"                                                       \
        :: "r"(addr), "r"(parity) : "memory");                                \
} while (0)

// ---- packed f32x2 helpers ---------------------------------------------------
__device__ __forceinline__ uint64_t pk2(float lo, float hi) {
    uint64_t r;
    asm("mov.b64 %0, {%1, %2};" : "=l"(r) : "f"(lo), "f"(hi));
    return r;
}
__device__ __forceinline__ uint64_t ffma2(uint64_t a, uint64_t b, uint64_t c) {
    uint64_t d;
    asm("fma.rn.f32x2 %0, %1, %2, %3;" : "=l"(d) : "l"(a), "l"(b), "l"(c));
    return d;
}
__device__ __forceinline__ uint64_t fadd2(uint64_t a, uint64_t b) {
    uint64_t d;
    asm("add.rn.f32x2 %0, %1, %2;" : "=l"(d) : "l"(a), "l"(b));
    return d;
}

// ---- packed (2-row) gate helpers (validated R4/R7/R8) ----------------------
__device__ __forceinline__ void ry_pair(float a[8], int i0, int i1, float c, float s) {
    float re0 = a[2*i0], im0 = a[2*i0+1], re1 = a[2*i1], im1 = a[2*i1+1];
    a[2*i0]   = c*re0 - s*re1;
    a[2*i0+1] = c*im0 - s*im1;
    a[2*i1]   = s*re0 + c*re1;
    a[2*i1+1] = s*im0 + c*im1;
}
__device__ __forceinline__ void ry_shfl(float a[8], int m, float c, float s, unsigned lane) {
    float sg = (lane & (unsigned)m) ? s : -s;
#pragma unroll
    for (int k = 0; k < 4; k++) {
        float orr = __shfl_xor_sync(0xFFFFFFFFu, a[2*k],   m);
        float oii = __shfl_xor_sync(0xFFFFFFFFu, a[2*k+1], m);
        a[2*k]   = c*a[2*k]   + sg*orr;
        a[2*k+1] = c*a[2*k+1] + sg*oii;
    }
}
__device__ __forceinline__ void apply_ry(int w, float a[8], float c, float s, unsigned lane) {
    if (w == 0)      { ry_pair(a, 0, 2, c, s); ry_pair(a, 1, 3, c, s); }
    else if (w == 1) { ry_pair(a, 0, 1, c, s); ry_pair(a, 2, 3, c, s); }
    else             ry_shfl(a, 1 << (5 - w), c, s, lane);
}

__device__ __forceinline__ void apply_cnot_ring(int q, float a[8], unsigned lane) {
    if (q == 0) {
        float t;
        t = a[4]; a[4] = a[6]; a[6] = t;
        t = a[5]; a[5] = a[7]; a[7] = t;
    } else if (q == 1) {
#pragma unroll
        for (int k = 1; k < 4; k += 2) {
            a[2*k]   = __shfl_xor_sync(0xFFFFFFFFu, a[2*k],   8);
            a[2*k+1] = __shfl_xor_sync(0xFFFFFFFFu, a[2*k+1], 8);
        }
    } else if (q == 5) {
        if (lane & 1u) {
            float t;
            t = a[0]; a[0] = a[4]; a[4] = t;
            t = a[1]; a[1] = a[5]; a[5] = t;
            t = a[2]; a[2] = a[6]; a[6] = t;
            t = a[3]; a[3] = a[7]; a[7] = t;
        }
    } else {
        int cb = 1 << (5 - q);
        int tm = 1 << (4 - q);
        bool ctrl = (lane & (unsigned)cb) != 0;
#pragma unroll
        for (int k = 0; k < 4; k++) {
            float vr = __shfl_xor_sync(0xFFFFFFFFu, a[2*k],   tm);
            float vi = __shfl_xor_sync(0xFFFFFFFFu, a[2*k+1], tm);
            if (ctrl) { a[2*k] = vr; a[2*k+1] = vi; }
        }
    }
}

// ---- full sim for one row (half-warp); q written duplicated ----------------
__device__ __forceinline__ void sim_rows(
    const float* __restrict__ x, const float* swc, const float* sws,
    float* sqdst, int trow, int b, unsigned lane, unsigned lane16) {
    float cx[NQ], sx[NQ];
#pragma unroll
    for (int j = 0; j < NQ; j++) {
        __sincosf(__ldg(&x[b * NQ + j]) * 0.5f, &sx[j], &cx[j]);
    }

    // per-wire v = RZ*RY*RX|0>
    float v0r[NQ], v0i[NQ], v1r[NQ], v1i[NQ];
#pragma unroll
    for (int iw = 0; iw < NQ; iw++) {
        int j1 = (iw + 1 > 5) ? iw - 5 : iw + 1;
        int j2 = (iw + 2 > 5) ? iw - 4 : iw + 2;
        float ar = cx[j1] * cx[iw];
        float ai = sx[j1] * sx[iw];
        float br = sx[j1] * cx[iw];
        float bi = -cx[j1] * sx[iw];
        float cz = cx[j2], sz = sx[j2];
        v0r[iw] = ar * cz + ai * sz;
        v0i[iw] = ai * cz - ar * sz;
        v1r[iw] = br * cz - bi * sz;
        v1i[iw] = bi * cz + br * sz;
    }

    // f = prod over wires 2..5; wire w bit = lane16 bit (5-w)
    float fr, fi;
    {
        bool bs = (lane16 & 8u) != 0;
        fr = bs ? v1r[2] : v0r[2];
        fi = bs ? v1i[2] : v0i[2];
    }
#pragma unroll
    for (int w2 = 3; w2 <= 5; w2++) {
        bool bs = (lane16 & (1u << (5 - w2))) != 0;
        float tr = bs ? v1r[w2] : v0r[w2];
        float ti = bs ? v1i[w2] : v0i[w2];
        float nr = fr * tr - fi * ti;
        float ni = fr * ti + fi * tr;
        fr = nr; fi = ni;
    }

    float a[8];
#pragma unroll
    for (int k = 0; k < 4; k++) {
        float u0r = (k & 2) ? v1r[0] : v0r[0];
        float u0i = (k & 2) ? v1i[0] : v0i[0];
        float u1r = (k & 1) ? v1r[1] : v0r[1];
        float u1i = (k & 1) ? v1i[1] : v0i[1];
        float gr = u0r * u1r - u0i * u1i;
        float gi = u0r * u1i + u0i * u1r;
        a[2*k]   = gr * fr - gi * fi;
        a[2*k+1] = gr * fi + gi * fr;
    }

#pragma unroll
    for (int l = 0; l < NLAYERS; l++) {
#pragma unroll
        for (int q = 0; q < NQ; q++)
            apply_ry(q, a, swc[l * NQ + q], sws[l * NQ + q], lane);
#pragma unroll
        for (int q = 0; q < NQ; q++) apply_cnot_ring(q, a, lane);
    }

    float p0 = a[0]*a[0] + a[1]*a[1];
    float p1 = a[2]*a[2] + a[3]*a[3];
    float p2 = a[4]*a[4] + a[5]*a[5];
    float p3 = a[6]*a[6] + a[7]*a[7];
    float ptot = p0 + p1 + p2 + p3;

    float e[NQ];
    e[0] = (p0 + p1) - (p2 + p3);
    e[1] = (p0 - p1) + (p2 - p3);
#pragma unroll
    for (int j = 2; j < NQ; j++) {
        float sg = (lane16 & (unsigned)(1 << (5 - j))) ? -1.0f : 1.0f;
        e[j] = sg * ptot;
    }
#pragma unroll
    for (int off = 8; off; off >>= 1) {
#pragma unroll
        for (int j = 0; j < NQ; j++)
            e[j] += __shfl_xor_sync(0xFFFFFFFFu, e[j], off);
    }
    if (lane16 == 0) {
#pragma unroll
        for (int j = 0; j < NQ; j++) {
            sqdst[trow * SQROW + 2 * j]     = e[j];
            sqdst[trow * SQROW + 2 * j + 1] = e[j];
        }
    }
}

// ---- fused persistent kernel ------------------------------------------------
__global__ __launch_bounds__(NTHREADS, 2)
void fused_kernel(const float* __restrict__ x,
                  const float* __restrict__ hx,
                  const float* __restrict__ qw,    // (3,6)
                  const float* __restrict__ fc_w,  // (1024,6)
                  const float* __restrict__ fc_b,  // (1024,)
                  float* __restrict__ out,
                  int B, int ntiles) {
    __shared__ float sq[2 * TR * SQROW];
    __shared__ float swc[NLAYERS * NQ];
    __shared__ float sws[NLAYERS * NQ];
    __shared__ __align__(8) uint64_t mb[4];

    const int tid = threadIdx.x;
    const int warp = tid >> 5;
    const unsigned lane = tid & 31u;
    const unsigned lane16 = lane & 15u;
    const int half = (int)(lane >> 4);
    const int stride = gridDim.x;
    const bool is_stream = (warp >= NSIMW);
    const int st = tid - NSIMW * 32;       // stream thread id 0..255

    const uint32_t mb_base = (uint32_t)__cvta_generic_to_shared(mb);
    const uint32_t full0  = mb_base;
    const uint32_t full1  = mb_base + 8;
    const uint32_t empty0 = mb_base + 16;
    const uint32_t empty1 = mb_base + 24;

    // ---- stream threads: fc weights + bias as packed f32x2 registers ----
    uint64_t w0l=0,w0h=0,w1l=0,w1h=0,w2l=0,w2h=0,w3l=0,w3h=0,w4l=0,w4h=0,w5l=0,w5h=0;
    uint64_t bvl=0, bvh=0;
    if (is_stream) {
        const int h0 = 4 * st;
        w0l = pk2(__ldg(&fc_w[(h0+0)*NQ+0]), __ldg(&fc_w[(h0+1)*NQ+0]));
        w0h = pk2(__ldg(&fc_w[(h0+2)*NQ+0]), __ldg(&fc_w[(h0+3)*NQ+0]));
        w1l = pk2(__ldg(&fc_w[(h0+0)*NQ+1]), __ldg(&fc_w[(h0+1)*NQ+1]));
        w1h = pk2(__ldg(&fc_w[(h0+2)*NQ+1]), __ldg(&fc_w[(h0+3)*NQ+1]));
        w2l = pk2(__ldg(&fc_w[(h0+0)*NQ+2]), __ldg(&fc_w[(h0+1)*NQ+2]));
        w2h = pk2(__ldg(&fc_w[(h0+2)*NQ+2]), __ldg(&fc_w[(h0+3)*NQ+2]));
        w3l = pk2(__ldg(&fc_w[(h0+0)*NQ+3]), __ldg(&fc_w[(h0+1)*NQ+3]));
        w3h = pk2(__ldg(&fc_w[(h0+2)*NQ+3]), __ldg(&fc_w[(h0+3)*NQ+3]));
        w4l = pk2(__ldg(&fc_w[(h0+0)*NQ+4]), __ldg(&fc_w[(h0+1)*NQ+4]));
        w4h = pk2(__ldg(&fc_w[(h0+2)*NQ+4]), __ldg(&fc_w[(h0+3)*NQ+4]));
        w5l = pk2(__ldg(&fc_w[(h0+0)*NQ+5]), __ldg(&fc_w[(h0+1)*NQ+5]));
        w5h = pk2(__ldg(&fc_w[(h0+2)*NQ+5]), __ldg(&fc_w[(h0+3)*NQ+5]));
        bvl = pk2(__ldg(&fc_b[h0+0]), __ldg(&fc_b[h0+1]));
        bvh = pk2(__ldg(&fc_b[h0+2]), __ldg(&fc_b[h0+3]));
    }
    if (tid < NLAYERS * NQ) {
        float s, c;
        __sincosf(__ldg(&qw[tid]) * 0.5f, &s, &c);
        swc[tid] = c; sws[tid] = s;
    }
    if (tid == 0) {
        MBAR_INIT(full0, 8);       // 8 writer half-warps per tile
        MBAR_INIT(full1, 8);
        MBAR_INIT(empty0, 256);    // 256 stream threads per tile
        MBAR_INIT(empty1, 256);
    }
    __syncthreads();               // one-time setup

    const int t0 = blockIdx.x;

    if (is_stream) {
        uint64_t hAl[HT], hAh[HT], hBl[HT], hBh[HT];

        // load half A of a tile (rows r0..r0+3)
        auto loadA = [&](int row0) {
#pragma unroll
            for (int r = 0; r < HT; r++) {
                int gb = min(row0 + r, B - 1);
                const float* src = hx + (size_t)gb * HDIM + 4 * st;
                asm volatile("ld.global.cs.v2.u64 {%0, %1}, [%2];"
                             : "=l"(hAl[r]), "=l"(hAh[r]) : "l"(src));
            }
        };
        auto loadB = [&](int row0) {
#pragma unroll
            for (int r = 0; r < HT; r++) {
                int gb = min(row0 + HT + r, B - 1);
                const float* src = hx + (size_t)gb * HDIM + 4 * st;
                asm volatile("ld.global.cs.v2.u64 {%0, %1}, [%2];"
                             : "=l"(hBl[r]), "=l"(hBh[r]) : "l"(src));
            }
        };

        // FMA+store `HT` rows starting at row0 from (hl, hh) using sqr rows r0off..
        auto fma_half = [&](int row0, int r0off, const float* sqr,
                            uint64_t* hl, uint64_t* hh) {
#pragma unroll
            for (int r = 0; r < HT; r++) {
                int b = row0 + r;
                if (b >= B) break;
                const float* qr = &sqr[(r0off + r) * SQROW];
                ulonglong2 q01 = *(const ulonglong2*)&qr[0];
                ulonglong2 q23 = *(const ulonglong2*)&qr[4];
                ulonglong2 q45 = *(const ulonglong2*)&qr[8];

                uint64_t lo = ffma2(q01.x, w0l, bvl);
                uint64_t hi = ffma2(q01.x, w0h, bvh);
                lo = ffma2(q01.y, w1l, lo);  hi = ffma2(q01.y, w1h, hi);
                lo = ffma2(q23.x, w2l, lo);  hi = ffma2(q23.x, w2h, hi);
                lo = ffma2(q23.y, w3l, lo);  hi = ffma2(q23.y, w3h, hi);
                lo = ffma2(q45.x, w4l, lo);  hi = ffma2(q45.x, w4h, hi);
                lo = ffma2(q45.y, w5l, lo);  hi = ffma2(q45.y, w5h, hi);
                lo = fadd2(lo, hl[r]);
                hi = fadd2(hi, hh[r]);

                float* dst = out + (size_t)b * HDIM + 4 * st;
                asm volatile("st.global.cs.v2.b64 [%0], {%1, %2};"
                             :: "l"(dst), "l"(lo), "l"(hi) : "memory");
            }
        };

        // prologue: load half A of first tile
        loadA(t0 * TR);

        int it = 0;
        for (int t = t0; t < ntiles; t += stride, it++) {
            const int row0 = t * TR;
            const int slot = it & 1;

            // issue half B loads (in flight during FMA of half A)
            loadB(row0);

            // wait for sim's q for tile t
            MBAR_WAIT(slot ? full1 : full0, (it >> 1) & 1);
            const float* sqr = &sq[slot * (TR * SQROW)];

            // FMA+store half A while B's loads are pending
            fma_half(row0, 0, sqr, hAl, hAh);

            // issue next tile's half-A loads (independent of next q)
            int tn = t + stride;
            if (tn < ntiles) loadA(tn * TR);

            // FMA+store half B while next tile's A loads are pending
            fma_half(row0 + HT, HT, sqr, hBl, hBh);

            // release sq slot
            MBAR_ARRIVE(slot ? empty1 : empty0);
        }
    } else {
        // ---- sim warps: independent loop, <=2 tiles ahead of stream ----
        const int trow = warp * 2 + half;
        int it = 0;
        for (int t = t0; t < ntiles; t += stride, it++) {
            const int slot = it & 1;
            MBAR_WAIT(slot ? empty1 : empty0, ((it >> 1) & 1) ^ 1);

            sim_rows(x, swc, sws, &sq[slot * (TR * SQROW)], trow,
                     min(t * TR + trow, B - 1), lane, lane16);

            if (lane16 == 0)
                MBAR_ARRIVE(slot ? full1 : full0);
        }
    }
}

// ---- launch ----------------------------------------------------------------
extern "C" void kernel_launch(void* const* d_in, const int* in_sizes, int n_in,
                              void* d_out, int out_size) {
    const float* x    = (const float*)d_in[0];   // (B,6)
    const float* hx   = (const float*)d_in[1];   // (B,1024)
    const float* qw   = (const float*)d_in[2];   // (3,6)
    const float* fc_w = (const float*)d_in[3];   // (1024,6)
    const float* fc_b = (const float*)d_in[4];   // (1024,)
    float* out = (float*)d_out;

    int B = in_sizes[0] / NQ;
    int ntiles = (B + TR - 1) / TR;

    int grid = 148 * 2;
    if (grid > ntiles) grid = ntiles;
    fused_kernel<<<grid, NTHREADS>>>(x, hx, qw, fc_w, fc_b, out, B, ntiles);
}